// round 8
// baseline (speedup 1.0000x reference)
#include <cuda_runtime.h>
#include <cuda_bf16.h>
#include <math.h>
#include <stdint.h>

#define T_LEN 131072
#define NS 64
#define MD 8
#define NCH1 888          // 2 chunks per CTA * 444 CTAs (3 CTAs/SM)
#define NCH3 148          // after 6-chain combine
#define L_BASE 147        // 131071 = 888*147 + 535
#define L_REM 535         // first 535 chunks have length 148

// ---- static device scratch ----
__device__ float g_wf[(size_t)T_LEN * NS];    // fragment-ordered weights: [t][r*8+k] = w[t][k*8+r]
__device__ float g_maxlog[T_LEN];
__device__ float g_loglam[NS * MD];
__device__ float g_lamsum[NS];
__device__ float g_Alin[NS * NS];
__device__ float g_M1[(size_t)NCH1 * NS * NS];   // natural layout: [c][i][j]
__device__ float g_M3[(size_t)NCH3 * NS * NS];   // P-layout: [c][j][i] = R[i][j]
__device__ float g_S1[NCH1];
__device__ float g_S3[NCH3];
__device__ unsigned int g_hist[32];

// ================= helpers =================
__device__ __forceinline__ uint32_t smem_u32(const void* p) {
    uint32_t a;
    asm("{ .reg .u64 t; cvta.to.shared.u64 t, %1; cvt.u32.u64 %0, t; }" : "=r"(a) : "l"(p));
    return a;
}
#define SW128(o) ((uint32_t)(o) ^ ((((uint32_t)(o)) >> 3) & 0x70u))
#define CVT_BF2(r, lo, hi) asm("cvt.rn.bf16x2.f32 %0, %1, %2;" : "=r"(r) : "f"(hi), "f"(lo))
#define STS32(v, a) asm volatile("st.shared.b32 [%0], %1;" :: "r"(a), "r"(v) : "memory")
#define LDSM_X4(r0, r1, r2, r3, a) \
    asm volatile("ldmatrix.sync.aligned.m8n8.x4.shared.b16 {%0,%1,%2,%3}, [%4];" \
                 : "=r"(r0), "=r"(r1), "=r"(r2), "=r"(r3) : "r"(a))
#define LDSM_X4_T(r0, r1, r2, r3, a) \
    asm volatile("ldmatrix.sync.aligned.m8n8.x4.trans.shared.b16 {%0,%1,%2,%3}, [%4];" \
                 : "=r"(r0), "=r"(r1), "=r"(r2), "=r"(r3) : "r"(a))
#define MMA_BF16(d, a, b0, b1) \
    asm volatile("mma.sync.aligned.m16n8k16.row.col.f32.bf16.bf16.f32 " \
                 "{%0,%1,%2,%3}, {%4,%5,%6,%7}, {%8,%9}, {%0,%1,%2,%3};" \
                 : "+f"((d)[0]), "+f"((d)[1]), "+f"((d)[2]), "+f"((d)[3]) \
                 : "r"((a)[0]), "r"((a)[1]), "r"((a)[2]), "r"((a)[3]), "r"(b0), "r"(b1))

__device__ __forceinline__ int chunk_t0(int c) { return 1 + c * L_BASE + (c < L_REM ? c : L_REM); }
__device__ __forceinline__ int chunk_len(int c) { return L_BASE + (c < L_REM ? 1 : 0); }

// ============================================================
__global__ void setup_kernel(const float* __restrict__ lambdas,
                             const float* __restrict__ log_transition) {
    int tid = threadIdx.x;
    for (int idx = tid; idx < NS * MD; idx += blockDim.x)
        g_loglam[idx] = logf(lambdas[idx]);
    if (tid < NS) {
        float s = 0.f;
        #pragma unroll
        for (int m = 0; m < MD; m++) s += lambdas[tid * MD + m];
        g_lamsum[tid] = s;
    }
    for (int idx = tid; idx < NS * NS; idx += blockDim.x)
        g_Alin[idx] = expf(log_transition[idx]);
    if (tid < 32) g_hist[tid] = 0u;
}

// ============================================================
__global__ void __launch_bounds__(256) pass0_kernel(const int* __restrict__ x) {
    __shared__ float sll[NS * MD];
    __shared__ float slam[NS];
    __shared__ unsigned int shist[32];
    int tid = threadIdx.x;
    for (int idx = tid; idx < NS * MD; idx += blockDim.x) sll[idx] = g_loglam[idx];
    if (tid < NS) slam[tid] = g_lamsum[tid];
    if (tid < 32) shist[tid] = 0u;
    __syncthreads();

    int warp = tid >> 5, lane = tid & 31;
    int t = blockIdx.x * 8 + warp;

    int4 xa = *(const int4*)&x[(size_t)t * MD];
    int4 xb = *(const int4*)&x[(size_t)t * MD + 4];
    int xv[8] = {xa.x, xa.y, xa.z, xa.w, xb.x, xb.y, xb.z, xb.w};
    if (lane < 8) atomicAdd(&shist[xv[lane] & 31], 1u);

    float e0 = -slam[lane], e1 = -slam[lane + 32];
    #pragma unroll
    for (int m = 0; m < 8; m++) {
        float xm = (float)xv[m];
        e0 = fmaf(xm, sll[lane * MD + m], e0);
        e1 = fmaf(xm, sll[(lane + 32) * MD + m], e1);
    }
    float mx = fmaxf(e0, e1);
    #pragma unroll
    for (int o = 16; o > 0; o >>= 1)
        mx = fmaxf(mx, __shfl_xor_sync(0xffffffffu, mx, o));
    // fragment-ordered store: state s -> slot (s&7)*8 + (s>>3)
    g_wf[(size_t)t * NS + (lane & 7) * 8 + (lane >> 3)]     = expf(e0 - mx);
    g_wf[(size_t)t * NS + (lane & 7) * 8 + (lane >> 3) + 4] = expf(e1 - mx);
    if (lane == 0) g_maxlog[t] = mx;

    __syncthreads();
    if (tid < 32 && shist[tid]) atomicAdd(&g_hist[tid], shist[tid]);
}

// ============================================================
// Pass 1: TWO chunks per CTA, 4 warps, warp-autonomous steps with the
// two chunks' dependency chains interleaved inside each warp (2x ILP).
// Warp w owns output cols [16w,16w+16) of BOTH chunk tiles.
// Renorm every 8 steps (+ each chunk's last step) = only cross-warp sync.
// ============================================================
#define RENORM_MASK 7
__global__ void __launch_bounds__(128, 3) pass1_mma() {
    __shared__ __align__(1024) unsigned char sAraw[NS * 128];
    __shared__ __align__(1024) unsigned char sMraw[2][NS * 128];  // [chunk][...]
    __shared__ float wmax[2][2][4];   // [parity][chunk][warp]

    int tid = threadIdx.x, lane = tid & 31, wid = tid >> 5;
    int ca = blockIdx.x * 2, cb = ca + 1;
    int t0a = chunk_t0(ca), t0b = chunk_t0(cb);
    int na = chunk_len(ca), nb = chunk_len(cb);   // na >= nb

    uint32_t sA = smem_u32(sAraw), sM = smem_u32(sMraw[0]);

    // A -> bf16 swizzled SMEM
    for (int idx = tid; idx < NS * NS; idx += 128) {
        int i = idx >> 6, k = idx & 63;
        *(__nv_bfloat16*)(sAraw + SW128(i * 128 + k * 2)) = __float2bfloat16(g_Alin[idx]);
    }
    // both tiles = zero
    for (int idx = tid; idx < (2 * NS * 128) / 4; idx += 128)
        ((uint32_t*)sMraw[0])[idx] = 0u;
    __syncthreads();
    {   // identity in both tiles
        int q = tid >> 6, j = tid & 63;
        *(__nv_bfloat16*)(sMraw[q] + SW128(j * 128 + j * 2)) = __float2bfloat16(1.0f);
    }
    __syncthreads();

    // Register-resident A fragments
    uint32_t afr[4][4][4];
    {
        int g = lane >> 3, r = lane & 7;
        #pragma unroll
        for (int mt = 0; mt < 4; mt++)
            #pragma unroll
            for (int kt = 0; kt < 4; kt++) {
                int row = mt * 16 + (g & 1) * 8 + r;
                int col = kt * 16 + (g >> 1) * 8;
                LDSM_X4(afr[mt][kt][0], afr[mt][kt][1], afr[mt][kt][2], afr[mt][kt][3],
                        sA + SW128(row * 128 + col * 2));
            }
    }
    // B ldmatrix addresses for chunk A tile; chunk B tile = +8192
    uint32_t baddr[4];
    {
        int g = lane >> 3, r = lane & 7;
        #pragma unroll
        for (int kt = 0; kt < 4; kt++) {
            int row = kt * 16 + (g & 1) * 8 + r;
            int col = wid * 16 + (g >> 1) * 8;
            baddr[kt] = sM + SW128(row * 128 + col * 2);
        }
    }

    int r0b = lane >> 2;            // 0..7
    int cpair = (lane & 3) * 2;     // 0,2,4,6
    float SA = 0.f, SB = 0.f;
    float invA = 1.0f, invB = 1.0f;

    for (int step = 0; step < na; step++) {
        bool lastA = (step == na - 1);
        bool actB  = (step < nb);
        bool lastB = (step == nb - 1);
        bool rsync = ((step & RENORM_MASK) == RENORM_MASK) || lastA || lastB;

        // weights (fragment-ordered, 2x LDG.128 per chunk; prefetched before MMA)
        const float4* wpa = (const float4*)&g_wf[(size_t)(t0a + step) * NS + r0b * 8];
        float4 wa0 = wpa[0], wa1 = wpa[1];
        float4 wb0, wb1;
        if (actB) {
            const float4* wpb = (const float4*)&g_wf[(size_t)(t0b + step) * NS + r0b * 8];
            wb0 = wpb[0]; wb1 = wpb[1];
        }
        float mlA = (tid == 0) ? g_maxlog[t0a + step] : 0.f;
        float mlB = (tid == 0 && actB) ? g_maxlog[t0b + step] : 0.f;

        float accA[4][2][4], accB[4][2][4];
        #pragma unroll
        for (int mt = 0; mt < 4; mt++)
            #pragma unroll
            for (int nt = 0; nt < 2; nt++)
                #pragma unroll
                for (int e = 0; e < 4; e++) { accA[mt][nt][e] = 0.f; accB[mt][nt][e] = 0.f; }

        // interleaved dual-chunk MMA: two independent chains per warp
        #pragma unroll
        for (int kt = 0; kt < 4; kt++) {
            uint32_t a0, a1, a2, a3, b0, b1, b2, b3;
            LDSM_X4_T(a0, a1, a2, a3, baddr[kt]);
            if (actB) LDSM_X4_T(b0, b1, b2, b3, baddr[kt] + 8192u);
            #pragma unroll
            for (int mt = 0; mt < 4; mt++) {
                MMA_BF16(accA[mt][0], afr[mt][kt], a0, a1);
                MMA_BF16(accA[mt][1], afr[mt][kt], a2, a3);
            }
            if (actB) {
                #pragma unroll
                for (int mt = 0; mt < 4; mt++) {
                    MMA_BF16(accB[mt][0], afr[mt][kt], b0, b1);
                    MMA_BF16(accB[mt][1], afr[mt][kt], b2, b3);
                }
            }
        }

        // ---- chunk A: scale + writeback ----
        wa0.x *= invA; wa0.y *= invA; wa0.z *= invA; wa0.w *= invA;
        wa1.x *= invA; wa1.y *= invA; wa1.z *= invA; wa1.w *= invA;
        {
            float wlo[4] = {wa0.x, wa0.z, wa1.x, wa1.z};
            float whi[4] = {wa0.y, wa0.w, wa1.y, wa1.w};
            #pragma unroll
            for (int mt = 0; mt < 4; mt++)
                #pragma unroll
                for (int nt = 0; nt < 2; nt++) {
                    accA[mt][nt][0] *= wlo[mt]; accA[mt][nt][1] *= wlo[mt];
                    accA[mt][nt][2] *= whi[mt]; accA[mt][nt][3] *= whi[mt];
                }
        }
        if (!lastA) {
            #pragma unroll
            for (int mt = 0; mt < 4; mt++)
                #pragma unroll
                for (int nt = 0; nt < 2; nt++) {
                    int col = wid * 16 + nt * 8 + cpair;
                    uint32_t p0, p1;
                    CVT_BF2(p0, accA[mt][nt][0], accA[mt][nt][1]);
                    CVT_BF2(p1, accA[mt][nt][2], accA[mt][nt][3]);
                    STS32(p0, sM + SW128((mt * 16 + r0b) * 128 + col * 2));
                    STS32(p1, sM + SW128((mt * 16 + 8 + r0b) * 128 + col * 2));
                }
        }
        // ---- chunk B: scale + writeback ----
        if (actB) {
            wb0.x *= invB; wb0.y *= invB; wb0.z *= invB; wb0.w *= invB;
            wb1.x *= invB; wb1.y *= invB; wb1.z *= invB; wb1.w *= invB;
            float wlo[4] = {wb0.x, wb0.z, wb1.x, wb1.z};
            float whi[4] = {wb0.y, wb0.w, wb1.y, wb1.w};
            #pragma unroll
            for (int mt = 0; mt < 4; mt++)
                #pragma unroll
                for (int nt = 0; nt < 2; nt++) {
                    accB[mt][nt][0] *= wlo[mt]; accB[mt][nt][1] *= wlo[mt];
                    accB[mt][nt][2] *= whi[mt]; accB[mt][nt][3] *= whi[mt];
                }
            if (!lastB) {
                #pragma unroll
                for (int mt = 0; mt < 4; mt++)
                    #pragma unroll
                    for (int nt = 0; nt < 2; nt++) {
                        int col = wid * 16 + nt * 8 + cpair;
                        uint32_t p0, p1;
                        CVT_BF2(p0, accB[mt][nt][0], accB[mt][nt][1]);
                        CVT_BF2(p1, accB[mt][nt][2], accB[mt][nt][3]);
                        STS32(p0, sM + 8192u + SW128((mt * 16 + r0b) * 128 + col * 2));
                        STS32(p1, sM + 8192u + SW128((mt * 16 + 8 + r0b) * 128 + col * 2));
                    }
            }
        }

        if (rsync) {
            // reduce max for both active chunks (interleaved shuffles)
            float lmA = 0.f, lmB = 0.f;
            #pragma unroll
            for (int mt = 0; mt < 4; mt++)
                #pragma unroll
                for (int nt = 0; nt < 2; nt++)
                    #pragma unroll
                    for (int e = 0; e < 4; e++) {
                        lmA = fmaxf(lmA, accA[mt][nt][e]);
                        lmB = fmaxf(lmB, accB[mt][nt][e]);
                    }
            #pragma unroll
            for (int o = 16; o > 0; o >>= 1) {
                lmA = fmaxf(lmA, __shfl_xor_sync(0xffffffffu, lmA, o));
                lmB = fmaxf(lmB, __shfl_xor_sync(0xffffffffu, lmB, o));
            }
            int par = (step >> 3) & 1;
            if (lane == 0) { wmax[par][0][wid] = lmA; wmax[par][1][wid] = lmB; }
            __syncthreads();
            float sa = fmaxf(fmaxf(fmaxf(wmax[par][0][0], wmax[par][0][1]),
                                   fmaxf(wmax[par][0][2], wmax[par][0][3])), 1e-30f);
            invA = 1.0f / sa;
            if (tid == 0) SA += mlA + __logf(sa);
            if (actB) {
                float sb = fmaxf(fmaxf(fmaxf(wmax[par][1][0], wmax[par][1][1]),
                                       fmaxf(wmax[par][1][2], wmax[par][1][3])), 1e-30f);
                invB = 1.0f / sb;
                if (tid == 0) SB += mlB + __logf(sb);
                if (lastB) {
                    float* gd = g_M1 + (size_t)cb * (NS * NS);
                    #pragma unroll
                    for (int mt = 0; mt < 4; mt++)
                        #pragma unroll
                        for (int nt = 0; nt < 2; nt++) {
                            int col = wid * 16 + nt * 8 + cpair;
                            *(float2*)&gd[(mt * 16 + r0b) * NS + col] =
                                make_float2(accB[mt][nt][0] * invB, accB[mt][nt][1] * invB);
                            *(float2*)&gd[(mt * 16 + 8 + r0b) * NS + col] =
                                make_float2(accB[mt][nt][2] * invB, accB[mt][nt][3] * invB);
                        }
                }
            }
            if (lastA) {
                float* gd = g_M1 + (size_t)ca * (NS * NS);
                #pragma unroll
                for (int mt = 0; mt < 4; mt++)
                    #pragma unroll
                    for (int nt = 0; nt < 2; nt++) {
                        int col = wid * 16 + nt * 8 + cpair;
                        *(float2*)&gd[(mt * 16 + r0b) * NS + col] =
                            make_float2(accA[mt][nt][0] * invA, accA[mt][nt][1] * invA);
                        *(float2*)&gd[(mt * 16 + 8 + r0b) * NS + col] =
                            make_float2(accA[mt][nt][2] * invA, accA[mt][nt][3] * invA);
                    }
            }
        } else {
            invA = 1.0f; invB = 1.0f;
            if (tid == 0) { SA += mlA; if (actB) SB += mlB; }
        }
        __syncwarp(0xffffffffu);   // STS visible within warp before next LDSM
    }
    if (tid == 0) { g_S1[ca] = SA; g_S1[cb] = SB; }
}

// ============================================================
// 6-chain combine: R = M[6c+5] @ ... @ M[6c]; store R in P-layout.
// ============================================================
#define CPAD 68
__global__ void __launch_bounds__(256) combine6_kernel() {
    __shared__ float sX[NS * CPAD];
    __shared__ float sY[NS * CPAD];
    int c = blockIdx.x, tid = threadIdx.x;
    const float* M = g_M1 + (size_t)(6 * c) * NS * NS;

    // T = M0 (direct [k][j])
    for (int idx = tid; idx < NS * NS; idx += 256)
        sY[(idx >> 6) * CPAD + (idx & 63)] = M[idx];

    int x0 = (tid >> 4) << 2;
    int y0 = (tid & 15) << 2;
    float acc[4][4];

    #pragma unroll 1
    for (int ph = 1; ph <= 4; ph++) {
        const float* Mn = M + (size_t)ph * NS * NS;
        for (int idx = tid; idx < NS * NS; idx += 256)
            sX[(idx & 63) * CPAD + (idx >> 6)] = Mn[idx];   // Mn^T: sX[k][i]
        __syncthreads();
        #pragma unroll
        for (int a = 0; a < 4; a++)
            #pragma unroll
            for (int b = 0; b < 4; b++) acc[a][b] = 0.f;
        #pragma unroll 8
        for (int k = 0; k < NS; k++) {
            float4 av = *(const float4*)&sX[k * CPAD + x0];
            float4 bv = *(const float4*)&sY[k * CPAD + y0];
            float aa[4] = {av.x, av.y, av.z, av.w};
            float bb[4] = {bv.x, bv.y, bv.z, bv.w};
            #pragma unroll
            for (int a = 0; a < 4; a++)
                #pragma unroll
                for (int b = 0; b < 4; b++)
                    acc[a][b] = fmaf(aa[a], bb[b], acc[a][b]);
        }
        __syncthreads();
        #pragma unroll
        for (int a = 0; a < 4; a++)
            *(float4*)&sY[(x0 + a) * CPAD + y0] =
                make_float4(acc[a][0], acc[a][1], acc[a][2], acc[a][3]);
    }

    // final phase with M5: R^T[j][i] = sum_k T[k][j] * M5[i][k]
    {
        const float* Mn = M + (size_t)5 * NS * NS;
        for (int idx = tid; idx < NS * NS; idx += 256)
            sX[(idx & 63) * CPAD + (idx >> 6)] = Mn[idx];
        __syncthreads();
        #pragma unroll
        for (int a = 0; a < 4; a++)
            #pragma unroll
            for (int b = 0; b < 4; b++) acc[a][b] = 0.f;
        #pragma unroll 8
        for (int k = 0; k < NS; k++) {
            float4 av = *(const float4*)&sY[k * CPAD + x0];   // T[k][j]
            float4 bv = *(const float4*)&sX[k * CPAD + y0];   // M5^T[k][i]
            float aa[4] = {av.x, av.y, av.z, av.w};
            float bb[4] = {bv.x, bv.y, bv.z, bv.w};
            #pragma unroll
            for (int a = 0; a < 4; a++)
                #pragma unroll
                for (int b = 0; b < 4; b++)
                    acc[a][b] = fmaf(aa[a], bb[b], acc[a][b]);
        }
        float* dst = g_M3 + (size_t)c * NS * NS;   // P-layout [j][i]
        #pragma unroll
        for (int a = 0; a < 4; a++)
            *(float4*)&dst[(x0 + a) * NS + y0] =
                make_float4(acc[a][0], acc[a][1], acc[a][2], acc[a][3]);
    }
    if (tid == 0) {
        float s = 0.f;
        #pragma unroll
        for (int q = 0; q < 6; q++) s += g_S1[6 * c + q];
        g_S3[c] = s;
    }
}

// ============================================================
// Pass 2: serial matvec over 148 combined chunks (P-layout).
// ============================================================
__global__ void __launch_bounds__(256) pass2_kernel(const int* __restrict__ x,
                                                    const float* __restrict__ priors,
                                                    float* __restrict__ out) {
    __shared__ float alpha[NS];
    __shared__ float part[256];
    __shared__ float anew[NS];
    __shared__ float evec[NS];
    __shared__ float wm2[2];
    int tid = threadIdx.x;
    int i = tid & 63, q = tid >> 6;

    if (tid < NS) {
        float e = priors[tid] - g_lamsum[tid];
        #pragma unroll
        for (int m = 0; m < MD; m++)
            e = fmaf((float)x[m], g_loglam[tid * MD + m], e);
        evec[tid] = e;
    }
    __syncthreads();
    if (tid < NS) {
        float m = evec[tid];
        #pragma unroll
        for (int o = 16; o > 0; o >>= 1)
            m = fmaxf(m, __shfl_xor_sync(0xffffffffu, m, o));
        if ((tid & 31) == 0) wm2[tid >> 5] = m;
    }
    __syncthreads();
    float m0 = fmaxf(wm2[0], wm2[1]);
    if (tid < NS) alpha[tid] = expf(evec[tid] - m0);
    double logscale = (double)m0;
    __syncthreads();

    float buf[2][16];
    #pragma unroll
    for (int r = 0; r < 16; r++)
        buf[0][r] = g_M3[(size_t)(q * 16 + r) * NS + i];
    int pp = 0;
    for (int c = 0; c < NCH3; c++) {
        if (c + 1 < NCH3) {
            #pragma unroll
            for (int r = 0; r < 16; r++)
                buf[pp ^ 1][r] = g_M3[(size_t)(c + 1) * (NS * NS) + (size_t)(q * 16 + r) * NS + i];
        }
        float partial = 0.f;
        #pragma unroll
        for (int r = 0; r < 16; r++)
            partial = fmaf(buf[pp][r], alpha[q * 16 + r], partial);
        part[tid] = partial;
        __syncthreads();
        if (tid < NS) {
            float a4 = part[tid] + part[tid + 64] + part[tid + 128] + part[tid + 192];
            anew[tid] = a4;
            float m = a4;
            #pragma unroll
            for (int o = 16; o > 0; o >>= 1)
                m = fmaxf(m, __shfl_xor_sync(0xffffffffu, m, o));
            if ((tid & 31) == 0) wm2[tid >> 5] = m;
        }
        __syncthreads();
        float s = fmaxf(fmaxf(wm2[0], wm2[1]), 1e-35f);
        if (tid == 0) logscale += (double)g_S3[c] + log((double)s);
        if (tid < NS) alpha[tid] = anew[tid] / s;
        __syncthreads();
        pp ^= 1;
    }

    if (tid == 0) {
        double sum = 0.0;
        for (int k = 0; k < NS; k++) sum += (double)alpha[k];
        double lgam = 0.0;
        for (int b = 0; b < 32; b++) {
            unsigned int cnt = g_hist[b];
            if (cnt) lgam += (double)cnt * lgamma((double)b + 1.0);
        }
        out[0] = (float)(logscale + log(sum) - lgam);
    }
}

// ============================================================
extern "C" void kernel_launch(void* const* d_in, const int* in_sizes, int n_in,
                              void* d_out, int out_size) {
    const int*   x              = (const int*)d_in[0];
    const float* lambdas        = (const float*)d_in[1];
    const float* log_transition = (const float*)d_in[2];
    const float* priors         = (const float*)d_in[3];
    float* out = (float*)d_out;

    setup_kernel<<<1, 256>>>(lambdas, log_transition);
    pass0_kernel<<<T_LEN / 8, 256>>>(x);
    pass1_mma<<<NCH1 / 2, 128>>>();
    combine6_kernel<<<NCH3, 256>>>();
    pass2_kernel<<<1, 256>>>(x, priors, out);
}

// round 9
// speedup vs baseline: 2.9581x; 2.9581x over previous
#include <cuda_runtime.h>
#include <math.h>
#include <stdint.h>

#define T_LEN 131072
#define NS 64
#define MD 8
#define NCH 888           // chunks: 2 per CTA, 444 CTAs (3 CTAs/SM)
#define L_BASE 147        // 131071 = 888*147 + 535
#define L_REM 535         // first 535 chunks have length 148
#define BURN 64           // burn-in steps (Perron direction warm-up)

// ---- static device scratch ----
__device__ float g_w[(size_t)T_LEN * NS];     // w[t][s] = exp(em - max), natural order
__device__ float g_maxlog[T_LEN];
__device__ float g_loglam[NS * MD];
__device__ float g_lamsum[NS];
__device__ float g_Alin[NS * NS];
__device__ float g_S1[NCH];
__device__ unsigned int g_hist[32];

__device__ __forceinline__ int chunk_t0(int c) { return 1 + c * L_BASE + (c < L_REM ? c : L_REM); }
__device__ __forceinline__ int chunk_len(int c) { return L_BASE + (c < L_REM ? 1 : 0); }

#define BAR64(id) asm volatile("bar.sync %0, 64;" :: "r"(id) : "memory")

// ============================================================
__global__ void setup_kernel(const float* __restrict__ lambdas,
                             const float* __restrict__ log_transition) {
    int tid = threadIdx.x;
    for (int idx = tid; idx < NS * MD; idx += blockDim.x)
        g_loglam[idx] = logf(lambdas[idx]);
    if (tid < NS) {
        float s = 0.f;
        #pragma unroll
        for (int m = 0; m < MD; m++) s += lambdas[tid * MD + m];
        g_lamsum[tid] = s;
    }
    for (int idx = tid; idx < NS * NS; idx += blockDim.x)
        g_Alin[idx] = expf(log_transition[idx]);
    if (tid < 32) g_hist[tid] = 0u;
}

// ============================================================
// Pass 0: emission weights w[t][s] (natural order) + maxlog + x-histogram.
// ============================================================
__global__ void __launch_bounds__(256) pass0_kernel(const int* __restrict__ x) {
    __shared__ float sll[NS * MD];
    __shared__ float slam[NS];
    __shared__ unsigned int shist[32];
    int tid = threadIdx.x;
    for (int idx = tid; idx < NS * MD; idx += blockDim.x) sll[idx] = g_loglam[idx];
    if (tid < NS) slam[tid] = g_lamsum[tid];
    if (tid < 32) shist[tid] = 0u;
    __syncthreads();

    int warp = tid >> 5, lane = tid & 31;
    int t = blockIdx.x * 8 + warp;

    int4 xa = *(const int4*)&x[(size_t)t * MD];
    int4 xb = *(const int4*)&x[(size_t)t * MD + 4];
    int xv[8] = {xa.x, xa.y, xa.z, xa.w, xb.x, xb.y, xb.z, xb.w};
    if (lane < 8) atomicAdd(&shist[xv[lane] & 31], 1u);

    float e0 = -slam[lane], e1 = -slam[lane + 32];
    #pragma unroll
    for (int m = 0; m < 8; m++) {
        float xm = (float)xv[m];
        e0 = fmaf(xm, sll[lane * MD + m], e0);
        e1 = fmaf(xm, sll[(lane + 32) * MD + m], e1);
    }
    float mx = fmaxf(e0, e1);
    #pragma unroll
    for (int o = 16; o > 0; o >>= 1)
        mx = fmaxf(mx, __shfl_xor_sync(0xffffffffu, mx, o));
    g_w[(size_t)t * NS + lane]      = expf(e0 - mx);
    g_w[(size_t)t * NS + lane + 32] = expf(e1 - mx);
    if (lane == 0) g_maxlog[t] = mx;

    __syncthreads();
    if (tid < 32 && shist[tid]) atomicAdd(&g_hist[tid], shist[tid]);
}

// ============================================================
// Pass 1 (vector scan): 2 chunks per CTA, 64 threads each.
// Thread i holds A row i in registers. Per step:
//   alpha_new[i] = w_t[i] * (1/s_prev) * sum_k A[i][k] * alpha_u[k]
// where s_prev (1-norm of previous unnormalized alpha) is reduced in the
// shadow of the matvec. Ping-pong alpha buffers; one named 64-thread
// barrier per step. Burn-in of BURN steps from uniform gives the chunk's
// incoming direction (Perron contraction); chunk 0 starts exactly.
// Accumulates S_c = sum over territory of (log s_t + maxlog_t).
// ============================================================
__global__ void __launch_bounds__(128, 3) pass1_vec(const int* __restrict__ x,
                                                    const float* __restrict__ priors) {
    __shared__ float sal[2][2][NS];     // [chunk][parity][state]
    __shared__ float ssum[2][2][2];     // [chunk][parity][warp-half]
    __shared__ float sinit[2][2];       // chunk-0 max reduce scratch

    int tid = threadIdx.x;
    int ch = tid >> 6;                  // chunk slot in CTA
    int i = tid & 63;                   // state index
    int h = (tid >> 5) & 1;             // warp-half within chunk
    int lane = tid & 31;
    int c = blockIdx.x * 2 + ch;
    int t0 = chunk_t0(c);
    int L = chunk_len(c);
    int tb = (c == 0) ? 1 : t0 - BURN;
    int tend = t0 + L;
    int accfrom = (c == 0) ? 0 : t0;    // accumulate log s_{t-1} when t-1 >= accfrom
    int barid = ch + 1;

    // A row i -> 64 registers
    float arow[NS];
    {
        const float4* ap = (const float4*)&g_Alin[i * NS];
        #pragma unroll
        for (int q = 0; q < 16; q++) {
            float4 v = ap[q];
            arow[4 * q]     = v.x; arow[4 * q + 1] = v.y;
            arow[4 * q + 2] = v.z; arow[4 * q + 3] = v.w;
        }
    }

    float my_prev;     // my component of the (unnormalized) alpha
    float S = 0.f;
    if (c == 0) {
        // exact alpha0: e_i = prior + x0·loglam - lamsum, shifted by max
        float e = priors[i] - g_lamsum[i];
        #pragma unroll
        for (int m = 0; m < MD; m++)
            e = fmaf((float)x[m], g_loglam[i * MD + m], e);
        float mx = e;
        #pragma unroll
        for (int o = 16; o > 0; o >>= 1)
            mx = fmaxf(mx, __shfl_xor_sync(0xffffffffu, mx, o));
        if (lane == 0) sinit[ch][h] = mx;
        __syncthreads();
        mx = fmaxf(sinit[0][0], sinit[0][1]);
        my_prev = expf(e - mx);
        S = mx;
    } else {
        my_prev = 1.0f;   // uniform start; burn-in washes direction
        __syncthreads();  // match chunk-0 path (CTA-wide barrier)
    }
    sal[ch][0][i] = my_prev;
    __syncthreads();

    int p = 0;
    for (int t = tb; t < tend; t++) {
        // reduce s_{t-1} = 1-norm of previous alpha (off critical path)
        float r = my_prev;
        #pragma unroll
        for (int o = 16; o > 0; o >>= 1)
            r += __shfl_xor_sync(0xffffffffu, r, o);
        if (lane == 0) ssum[ch][p][h] = r;

        // prefetch this step's weights (coalesced 256B) + emission max
        float w = __ldg(&g_w[(size_t)t * NS + i]);
        float ml = g_maxlog[t];

        BAR64(barid);   // prev step's STS (buffer p) + ssum[p] visible

        // matvec: all threads broadcast-read alpha_u (buffer p)
        const float4* av = (const float4*)sal[ch][p];
        float a0 = 0.f, a1 = 0.f, a2 = 0.f, a3 = 0.f;
        #pragma unroll
        for (int q = 0; q < 16; q++) {
            float4 v = av[q];
            a0 = fmaf(arow[4 * q],     v.x, a0);
            a1 = fmaf(arow[4 * q + 1], v.y, a1);
            a2 = fmaf(arow[4 * q + 2], v.z, a2);
            a3 = fmaf(arow[4 * q + 3], v.w, a3);
        }
        float s = ssum[ch][p][0] + ssum[ch][p][1];
        float inv = __frcp_rn(s);
        float val = ((a0 + a1) + (a2 + a3)) * w * inv;
        sal[ch][p ^ 1][i] = val;
        my_prev = val;
        if (i == 0) {
            if (t - 1 >= accfrom) S += __logf(s);
            if (t >= t0) S += ml;
        }
        p ^= 1;
    }
    // final norm (after step tend-1)
    {
        float r = my_prev;
        #pragma unroll
        for (int o = 16; o > 0; o >>= 1)
            r += __shfl_xor_sync(0xffffffffu, r, o);
        if (lane == 0) ssum[ch][p][h] = r;
        BAR64(barid);
        if (i == 0) {
            float s = ssum[ch][p][0] + ssum[ch][p][1];
            g_S1[c] = S + __logf(s);
        }
    }
}

// ============================================================
// Final: out = sum_c S_c - sum lgamma(x+1)   (double accumulation)
// ============================================================
__global__ void __launch_bounds__(256) final_kernel(float* __restrict__ out) {
    __shared__ double sp[8];
    int tid = threadIdx.x, lane = tid & 31, wid = tid >> 5;
    double s = 0.0;
    for (int c = tid; c < NCH; c += 256) s += (double)g_S1[c];
    #pragma unroll
    for (int o = 16; o > 0; o >>= 1)
        s += __shfl_xor_sync(0xffffffffu, s, o);
    if (lane == 0) sp[wid] = s;
    __syncthreads();
    if (tid == 0) {
        double tot = 0.0;
        #pragma unroll
        for (int q = 0; q < 8; q++) tot += sp[q];
        double lgam = 0.0;
        for (int b = 0; b < 32; b++) {
            unsigned int cnt = g_hist[b];
            if (cnt) lgam += (double)cnt * lgamma((double)b + 1.0);
        }
        out[0] = (float)(tot - lgam);
    }
}

// ============================================================
extern "C" void kernel_launch(void* const* d_in, const int* in_sizes, int n_in,
                              void* d_out, int out_size) {
    const int*   x              = (const int*)d_in[0];
    const float* lambdas        = (const float*)d_in[1];
    const float* log_transition = (const float*)d_in[2];
    const float* priors         = (const float*)d_in[3];
    float* out = (float*)d_out;

    setup_kernel<<<1, 256>>>(lambdas, log_transition);
    pass0_kernel<<<T_LEN / 8, 256>>>(x);
    pass1_vec<<<NCH / 2, 128>>>(x, priors);
    final_kernel<<<1, 256>>>(out);
}